// round 1
// baseline (speedup 1.0000x reference)
#include <cuda_runtime.h>

// Problem constants
#define N_ROWS 16384
#define D_DIM  128
#define BM 64
#define BN 64
#define KSTRIDE 132   // padded fp32 stride for 64x128 tiles (conflict mitigation)
#define PSTRIDE 80    // padded stride for P tile: 80 mod 32 = 16 -> conflict-free

// Scratch: normalized rows + row norms (device globals: allocation-free rule)
__device__ float g_nx[N_ROWS * D_DIM];
__device__ float g_norm[N_ROWS];

// ---------------------------------------------------------------------------
// Pass 1: row-normalize x into g_nx, store norms in g_norm.
// One block per row, 128 threads.
// ---------------------------------------------------------------------------
__global__ void normalize_kernel(const float* __restrict__ x) {
    int row = blockIdx.x;
    float v = x[row * D_DIM + threadIdx.x];
    float ss = v * v;
    #pragma unroll
    for (int o = 16; o; o >>= 1) ss += __shfl_xor_sync(0xffffffffu, ss, o);
    __shared__ float red[4];
    if ((threadIdx.x & 31) == 0) red[threadIdx.x >> 5] = ss;
    __syncthreads();
    float tot = red[0] + red[1] + red[2] + red[3];
    float nrm = sqrtf(tot);
    float inv = 1.0f / fmaxf(nrm, 1e-12f);
    g_nx[row * D_DIM + threadIdx.x] = v * inv;
    if (threadIdx.x == 0) g_norm[row] = nrm;
}

// ---------------------------------------------------------------------------
// Pass 2: fused sim-softmax-aggregate-LayerNorm.
//   Per block: 64 query rows. Stream all 16384 keys in 64-row tiles.
//   Softmax logits are bounded in [-1,1] -> NO max subtraction needed:
//     x_neg_i = (sum_j e^{s_ij} * norm_j * nx_j) / (sum_j e^{s_ij})
//   Thread grid 16x16: ty=tid/16 (row group), tx=tid%16 (col group).
//   S micro-tile: rows {ty+16a}, cols {tx+16b}, a,b in 0..3.
//   O micro-tile: rows {ty+16a} x cols {tx+16b}, b in 0..7 (full D=128).
// ---------------------------------------------------------------------------
extern __shared__ float smem[];

__global__ __launch_bounds__(256, 2)
void attn_ln_kernel(const float* __restrict__ gamma,
                    const float* __restrict__ beta,
                    float* __restrict__ out) {
    float* q_s = smem;                       // BM * KSTRIDE
    float* k_s = q_s + BM * KSTRIDE;         // BN * KSTRIDE
    float* p_s = k_s + BN * KSTRIDE;         // BM * PSTRIDE
    float* qn  = p_s + BM * PSTRIDE;         // BM
    float* kn  = qn + BM;                    // BN

    const int tid = threadIdx.x;
    const int ty = tid >> 4;
    const int tx = tid & 15;
    const int i0 = blockIdx.x * BM;

    // Load Q tile (normalized rows) into padded smem; coalesced float4.
    for (int idx = tid; idx < BM * (D_DIM / 4); idx += 256) {
        int r = idx >> 5, c4 = idx & 31;
        float4 v = *(const float4*)(g_nx + (size_t)(i0 + r) * D_DIM + c4 * 4);
        *(float4*)(q_s + r * KSTRIDE + c4 * 4) = v;
    }
    if (tid < BM) qn[tid] = g_norm[i0 + tid];

    float o_acc[4][8];
    float den[4];
    #pragma unroll
    for (int a = 0; a < 4; a++) {
        den[a] = 0.0f;
        #pragma unroll
        for (int b = 0; b < 8; b++) o_acc[a][b] = 0.0f;
    }

    float gmr[8], btr[8];
    #pragma unroll
    for (int b = 0; b < 8; b++) {
        gmr[b] = gamma[tx + 16 * b];
        btr[b] = beta[tx + 16 * b];
    }

    __syncthreads();  // Q tile ready

    for (int t = 0; t < N_ROWS / BN; t++) {
        // Load K tile (normalized rows) + key norms.
        for (int idx = tid; idx < BN * (D_DIM / 4); idx += 256) {
            int r = idx >> 5, c4 = idx & 31;
            float4 v = *(const float4*)(g_nx + (size_t)(t * BN + r) * D_DIM + c4 * 4);
            *(float4*)(k_s + r * KSTRIDE + c4 * 4) = v;
        }
        if (tid < BN) kn[tid] = g_norm[t * BN + tid];
        __syncthreads();

        // ---- S = Q . K^T  (4x4 micro-tile per thread, float4 over d) ----
        float s[4][4];
        #pragma unroll
        for (int a = 0; a < 4; a++)
            #pragma unroll
            for (int b = 0; b < 4; b++) s[a][b] = 0.0f;

        #pragma unroll 8
        for (int d4 = 0; d4 < D_DIM / 4; d4++) {
            float4 qv[4], kv[4];
            #pragma unroll
            for (int a = 0; a < 4; a++)
                qv[a] = *(const float4*)(q_s + (ty + 16 * a) * KSTRIDE + d4 * 4);
            #pragma unroll
            for (int b = 0; b < 4; b++)
                kv[b] = *(const float4*)(k_s + (tx + 16 * b) * KSTRIDE + d4 * 4);
            #pragma unroll
            for (int a = 0; a < 4; a++)
                #pragma unroll
                for (int b = 0; b < 4; b++) {
                    s[a][b] += qv[a].x * kv[b].x;
                    s[a][b] += qv[a].y * kv[b].y;
                    s[a][b] += qv[a].z * kv[b].z;
                    s[a][b] += qv[a].w * kv[b].w;
                }
        }

        // ---- exp (bounded logits, no max), fold key norm into weight ----
        #pragma unroll
        for (int a = 0; a < 4; a++)
            #pragma unroll
            for (int b = 0; b < 4; b++) {
                float w = __expf(s[a][b]);
                den[a] += w;
                p_s[(ty + 16 * a) * PSTRIDE + tx + 16 * b] = w * kn[tx + 16 * b];
            }
        __syncthreads();

        // ---- O += P . NX  (reuse k_s as values) ----
        #pragma unroll 4
        for (int j = 0; j < BN; j++) {
            float pv[4], xv[8];
            #pragma unroll
            for (int a = 0; a < 4; a++) pv[a] = p_s[(ty + 16 * a) * PSTRIDE + j];
            #pragma unroll
            for (int b = 0; b < 8; b++) xv[b] = k_s[j * KSTRIDE + tx + 16 * b];
            #pragma unroll
            for (int a = 0; a < 4; a++)
                #pragma unroll
                for (int b = 0; b < 8; b++) o_acc[a][b] += pv[a] * xv[b];
        }
        __syncthreads();  // before next tile overwrites k_s / p_s
    }

    // ---- denominator: reduce partials across the 16 tx threads of each row ----
    #pragma unroll
    for (int a = 0; a < 4; a++) {
        #pragma unroll
        for (int o = 8; o; o >>= 1)
            den[a] += __shfl_xor_sync(0xffffffffu, den[a], o, 16);
    }

    // ---- y = 1.5*x - 0.5*x_neg, then LayerNorm per row ----
    #pragma unroll
    for (int a = 0; a < 4; a++) {
        int r = ty + 16 * a;
        float qnorm = qn[r];
        float inv_den = 1.0f / den[a];
        float y[8];
        float sum = 0.0f, sq = 0.0f;
        #pragma unroll
        for (int b = 0; b < 8; b++) {
            float xval = qnorm * q_s[r * KSTRIDE + tx + 16 * b];
            float xneg = o_acc[a][b] * inv_den;
            float yy = 1.5f * xval - 0.5f * xneg;
            y[b] = yy;
            sum += yy;
            sq += yy * yy;
        }
        #pragma unroll
        for (int o = 8; o; o >>= 1) {
            sum += __shfl_xor_sync(0xffffffffu, sum, o, 16);
            sq  += __shfl_xor_sync(0xffffffffu, sq, o, 16);
        }
        float mu  = sum * (1.0f / D_DIM);
        float var = sq * (1.0f / D_DIM) - mu * mu;
        float rstd = rsqrtf(var + 1e-5f);
        #pragma unroll
        for (int b = 0; b < 8; b++)
            out[(size_t)(i0 + r) * D_DIM + tx + 16 * b] =
                (y[b] - mu) * rstd * gmr[b] + btr[b];
    }
}

// ---------------------------------------------------------------------------
extern "C" void kernel_launch(void* const* d_in, const int* in_sizes, int n_in,
                              void* d_out, int out_size) {
    const float* x     = (const float*)d_in[0];
    const float* gamma = (const float*)d_in[1];
    const float* beta  = (const float*)d_in[2];
    float* out = (float*)d_out;

    normalize_kernel<<<N_ROWS, D_DIM>>>(x);

    const size_t smem_bytes =
        (size_t)(BM * KSTRIDE + BN * KSTRIDE + BM * PSTRIDE + BM + BN) * sizeof(float);
    cudaFuncSetAttribute(attn_ln_kernel,
                         cudaFuncAttributeMaxDynamicSharedMemorySize,
                         (int)smem_bytes);
    attn_ln_kernel<<<N_ROWS / BM, 256, smem_bytes>>>(gamma, beta, out);
}

// round 5
// speedup vs baseline: 9.7132x; 9.7132x over previous
#include <cuda_runtime.h>
#include <cuda_bf16.h>
#include <cstdint>

#define NROWS 16384
#define DD    128
#define BM    128
#define BN    128
#define NTILES (NROWS / BN)

// bf16 operands (device globals: allocation-free rule)
__device__ __nv_bfloat16 g_nx[NROWS * DD];   // normalized rows (Q/K)
__device__ __nv_bfloat16 g_xb[NROWS * DD];   // raw x in bf16 (V)

// ---------------------------------------------------------------------------
__device__ __forceinline__ uint32_t smem_u32(const void* p) {
    uint32_t a;
    asm("{ .reg .u64 t; cvta.to.shared.u64 t, %1; cvt.u32.u64 %0, t; }"
        : "=r"(a) : "l"(p));
    return a;
}
__device__ __forceinline__ void cpa16(uint32_t dst, const void* src) {
    asm volatile("cp.async.cg.shared.global [%0], [%1], 16;"
                 :: "r"(dst), "l"(src) : "memory");
}
#define CP_COMMIT() asm volatile("cp.async.commit_group;" ::: "memory")
#define CP_WAIT1()  asm volatile("cp.async.wait_group 1;" ::: "memory")
#define CP_WAIT0()  asm volatile("cp.async.wait_group 0;" ::: "memory")

__device__ __forceinline__ void ldsm4(uint32_t* r, uint32_t addr) {
    asm volatile("ldmatrix.sync.aligned.m8n8.x4.shared.b16 {%0,%1,%2,%3}, [%4];"
        : "=r"(r[0]), "=r"(r[1]), "=r"(r[2]), "=r"(r[3]) : "r"(addr));
}
__device__ __forceinline__ void ldsm4t(uint32_t* r, uint32_t addr) {
    asm volatile("ldmatrix.sync.aligned.m8n8.x4.trans.shared.b16 {%0,%1,%2,%3}, [%4];"
        : "=r"(r[0]), "=r"(r[1]), "=r"(r[2]), "=r"(r[3]) : "r"(addr));
}
__device__ __forceinline__ void mma16816(float* c, const uint32_t* a,
                                         uint32_t b0, uint32_t b1) {
    asm volatile("mma.sync.aligned.m16n8k16.row.col.f32.bf16.bf16.f32 "
        "{%0,%1,%2,%3}, {%4,%5,%6,%7}, {%8,%9}, {%0,%1,%2,%3};"
        : "+f"(c[0]), "+f"(c[1]), "+f"(c[2]), "+f"(c[3])
        : "r"(a[0]), "r"(a[1]), "r"(a[2]), "r"(a[3]), "r"(b0), "r"(b1));
}
// pack two fp32 -> bf16x2 (lo = first arg)
__device__ __forceinline__ uint32_t packbf(float lo, float hi) {
    uint32_t d;
    asm("cvt.rn.bf16x2.f32 %0, %1, %2;" : "=r"(d) : "f"(hi), "f"(lo));
    return d;
}
// Degree-7 Taylor exp, s in [-1,1]: rel err < 3e-5, pure FFMA
__device__ __forceinline__ float expp(float s) {
    float p = 1.9841270e-4f;
    p = fmaf(p, s, 1.3888889e-3f);
    p = fmaf(p, s, 8.3333333e-3f);
    p = fmaf(p, s, 4.1666667e-2f);
    p = fmaf(p, s, 1.6666667e-1f);
    p = fmaf(p, s, 0.5f);
    p = fmaf(p, s, 1.0f);
    p = fmaf(p, s, 1.0f);
    return p;
}

// Tile smem layout: row r (0..127) * 256B, 16B chunk c swizzled by row
__device__ __forceinline__ uint32_t toff(int r, int c) {
    return (uint32_t)(r * 256 + ((c ^ (r & 7)) << 4));
}

#define STG_K(s) ((s) * 65536)
#define STG_V(s) ((s) * 65536 + 32768)
#define SMEM_BYTES 131072

// ---------------------------------------------------------------------------
// Prepass: per row emit bf16 normalized (g_nx) and bf16 raw (g_xb).
// ---------------------------------------------------------------------------
__global__ void prep_kernel(const float* __restrict__ x) {
    int row  = blockIdx.x * 8 + (threadIdx.x >> 5);
    int lane = threadIdx.x & 31;
    float4 v = *(const float4*)(x + (size_t)row * DD + lane * 4);
    float ss = v.x * v.x + v.y * v.y + v.z * v.z + v.w * v.w;
    #pragma unroll
    for (int o = 16; o; o >>= 1) ss += __shfl_xor_sync(0xffffffffu, ss, o);
    float inv = 1.0f / fmaxf(sqrtf(ss), 1e-12f);
    size_t base = (size_t)row * DD + lane * 4;
    *(__nv_bfloat162*)(g_nx + base)     = __floats2bfloat162_rn(v.x * inv, v.y * inv);
    *(__nv_bfloat162*)(g_nx + base + 2) = __floats2bfloat162_rn(v.z * inv, v.w * inv);
    *(__nv_bfloat162*)(g_xb + base)     = __floats2bfloat162_rn(v.x, v.y);
    *(__nv_bfloat162*)(g_xb + base + 2) = __floats2bfloat162_rn(v.z, v.w);
}

// ---------------------------------------------------------------------------
__device__ __forceinline__ void prefetch_tile(int t, uint32_t sb, int tid) {
    if (t < NTILES) {
        uint32_t kb = sb + STG_K(t & 1);
        uint32_t vb = sb + STG_V(t & 1);
        int j0 = t * BN;
        #pragma unroll
        for (int i = 0; i < 8; i++) {
            int idx = tid + i * 256;
            int r = idx >> 4, c = idx & 15;
            size_t src = (size_t)(j0 + r) * DD + c * 8;
            uint32_t d = toff(r, c);
            cpa16(kb + d, g_nx + src);
            cpa16(vb + d, g_xb + src);
        }
    }
    CP_COMMIT();
}

// ---------------------------------------------------------------------------
// Fused attention + LayerNorm via mma.sync (FA2-style).
// ---------------------------------------------------------------------------
__global__ __launch_bounds__(256, 1)
void attn_kernel(const float* __restrict__ x,
                 const float* __restrict__ gamma,
                 const float* __restrict__ beta,
                 float* __restrict__ out) {
    extern __shared__ char smem[];
    uint32_t sb = smem_u32(smem);
    const int tid  = threadIdx.x;
    const int wid  = tid >> 5;
    const int lane = tid & 31;
    const int i0   = blockIdx.x * BM;

    // ---- stage Q tile (via cp.async into stage0 K area), load Q fragments ----
    {
        uint32_t kb = sb + STG_K(0);
        #pragma unroll
        for (int i = 0; i < 8; i++) {
            int idx = tid + i * 256;
            int r = idx >> 4, c = idx & 15;
            cpa16(kb + toff(r, c), g_nx + (size_t)(i0 + r) * DD + c * 8);
        }
        CP_COMMIT(); CP_WAIT0();
    }
    __syncthreads();

    uint32_t q[8][4];
    {
        int rbase = wid * 16 + (lane & 7) + ((lane >> 3) & 1) * 8;
        #pragma unroll
        for (int kk = 0; kk < 8; kk++) {
            int chunk = 2 * kk + (lane >> 4);
            ldsm4(q[kk], sb + STG_K(0) + toff(rbase, chunk));
        }
    }
    __syncthreads();

    prefetch_tile(0, sb, tid);
    prefetch_tile(1, sb, tid);

    float o[16][4];
    #pragma unroll
    for (int j = 0; j < 16; j++)
        #pragma unroll
        for (int c = 0; c < 4; c++) o[j][c] = 0.0f;
    float den0 = 0.0f, den1 = 0.0f;

    // ldmatrix lane-address components (computed once)
    const int klr  = lane & 7;
    const int kg1  = (lane >> 3) & 1;   // chunk parity for K / row-half for V
    const int kg2  = lane >> 4;         // row-half for K / chunk parity for V

    for (int t = 0; t < NTILES; t++) {
        uint32_t kb = sb + STG_K(t & 1);
        uint32_t vb = sb + STG_V(t & 1);
        CP_WAIT1();
        __syncthreads();

        // ---- S = Q.K^T per 16-key group, fused exp+pack ----
        uint32_t pk[32];
        #pragma unroll
        for (int g = 0; g < 8; g++) {
            float s0[4] = {0, 0, 0, 0}, s1[4] = {0, 0, 0, 0};
            int krow = g * 16 + kg2 * 8 + klr;
            #pragma unroll
            for (int kk = 0; kk < 8; kk++) {
                uint32_t b[4];
                ldsm4(b, kb + toff(krow, 2 * kk + kg1));
                mma16816(s0, q[kk], b[0], b[1]);
                mma16816(s1, q[kk], b[2], b[3]);
            }
            float e00 = expp(s0[0]), e01 = expp(s0[1]);
            float e02 = expp(s0[2]), e03 = expp(s0[3]);
            float e10 = expp(s1[0]), e11 = expp(s1[1]);
            float e12 = expp(s1[2]), e13 = expp(s1[3]);
            den0 += e00 + e01 + e10 + e11;
            den1 += e02 + e03 + e12 + e13;
            pk[4 * g + 0] = packbf(e00, e01);
            pk[4 * g + 1] = packbf(e02, e03);
            pk[4 * g + 2] = packbf(e10, e11);
            pk[4 * g + 3] = packbf(e12, e13);
        }

        // ---- O += P.V ----
        #pragma unroll
        for (int kk = 0; kk < 8; kk++) {
            int vrow = kk * 16 + kg1 * 8 + klr;
            #pragma unroll
            for (int dg = 0; dg < 8; dg++) {
                uint32_t v[4];
                ldsm4t(v, vb + toff(vrow, 2 * dg + kg2));
                mma16816(o[2 * dg],     &pk[4 * kk], v[0], v[1]);
                mma16816(o[2 * dg + 1], &pk[4 * kk], v[2], v[3]);
            }
        }

        __syncthreads();
        prefetch_tile(t + 2, sb, tid);
    }

    // ---- denominators: reduce within quad (4 lanes own each row) ----
    den0 += __shfl_xor_sync(0xffffffffu, den0, 1);
    den0 += __shfl_xor_sync(0xffffffffu, den0, 2);
    den1 += __shfl_xor_sync(0xffffffffu, den1, 1);
    den1 += __shfl_xor_sync(0xffffffffu, den1, 2);
    const float inv0 = 0.5f / den0;   // folds SCALE=-0.5
    const float inv1 = 0.5f / den1;

    const int r0 = wid * 16 + (lane >> 2);
    const size_t grow0 = (size_t)(i0 + r0) * DD;
    const size_t grow1 = grow0 + 8 * DD;

    // ---- y = 1.5x - 0.5*O/den (in place over o), partial LN sums ----
    float s10 = 0, s20 = 0, s11 = 0, s21 = 0;
    #pragma unroll
    for (int j = 0; j < 16; j++) {
        int col = 8 * j + (lane & 3) * 2;
        float2 xv0 = *(const float2*)(x + grow0 + col);
        float2 xv1 = *(const float2*)(x + grow1 + col);
        float y00 = fmaf(1.5f, xv0.x, -o[j][0] * inv0);
        float y01 = fmaf(1.5f, xv0.y, -o[j][1] * inv0);
        float y10 = fmaf(1.5f, xv1.x, -o[j][2] * inv1);
        float y11 = fmaf(1.5f, xv1.y, -o[j][3] * inv1);
        o[j][0] = y00; o[j][1] = y01; o[j][2] = y10; o[j][3] = y11;
        s10 += y00 + y01;           s11 += y10 + y11;
        s20 = fmaf(y00, y00, s20);  s20 = fmaf(y01, y01, s20);
        s21 = fmaf(y10, y10, s21);  s21 = fmaf(y11, y11, s21);
    }
    s10 += __shfl_xor_sync(0xffffffffu, s10, 1);
    s10 += __shfl_xor_sync(0xffffffffu, s10, 2);
    s20 += __shfl_xor_sync(0xffffffffu, s20, 1);
    s20 += __shfl_xor_sync(0xffffffffu, s20, 2);
    s11 += __shfl_xor_sync(0xffffffffu, s11, 1);
    s11 += __shfl_xor_sync(0xffffffffu, s11, 2);
    s21 += __shfl_xor_sync(0xffffffffu, s21, 1);
    s21 += __shfl_xor_sync(0xffffffffu, s21, 2);

    const float mu0 = s10 * (1.0f / DD);
    const float mu1 = s11 * (1.0f / DD);
    const float rs0 = rsqrtf(s20 * (1.0f / DD) - mu0 * mu0 + 1e-5f);
    const float rs1 = rsqrtf(s21 * (1.0f / DD) - mu1 * mu1 + 1e-5f);

    #pragma unroll
    for (int j = 0; j < 16; j++) {
        int col = 8 * j + (lane & 3) * 2;
        float2 gm = *(const float2*)(gamma + col);
        float2 bt = *(const float2*)(beta + col);
        float2 o0, o1;
        o0.x = fmaf((o[j][0] - mu0) * rs0, gm.x, bt.x);
        o0.y = fmaf((o[j][1] - mu0) * rs0, gm.y, bt.y);
        o1.x = fmaf((o[j][2] - mu1) * rs1, gm.x, bt.x);
        o1.y = fmaf((o[j][3] - mu1) * rs1, gm.y, bt.y);
        *(float2*)(out + grow0 + col) = o0;
        *(float2*)(out + grow1 + col) = o1;
    }
}

// ---------------------------------------------------------------------------
extern "C" void kernel_launch(void* const* d_in, const int* in_sizes, int n_in,
                              void* d_out, int out_size) {
    const float* x     = (const float*)d_in[0];
    const float* gamma = (const float*)d_in[1];
    const float* beta  = (const float*)d_in[2];
    float* out = (float*)d_out;

    prep_kernel<<<NROWS / 8, 256>>>(x);

    cudaFuncSetAttribute(attn_kernel,
                         cudaFuncAttributeMaxDynamicSharedMemorySize, SMEM_BYTES);
    attn_kernel<<<NROWS / BM, 256, SMEM_BYTES>>>(x, gamma, beta, out);
}